// round 7
// baseline (speedup 1.0000x reference)
#include <cuda_runtime.h>
#include <math.h>

#define NG        1536
#define WID       160
#define HEI       128
#define FX_       146.44f
#define FY_       146.44f
#define CX_       80.0f
#define CY_       64.0f
#define EPS2D_    0.3f
#define NEAR_     0.01f
#define FAR_      1e10f
#define NSEG      16
#define SEGLEN    (NG / NSEG)          // 96 (also max per-warp sublist length)
#define LOG2E_    1.4426950408889634f
#define SKIP_THR  (-16.0f)             // log2 units; culled alpha <= 1.5e-5
#define FINF      __int_as_float(0x7f800000)
#define NPART     4                    // rank-scan split factor
#define CHUNK     (NG / NPART)         // 384 keys per scanning thread

#define TILE_COLS 5                    // 32-px column strips
#define TILE_ROWS 16                   // 8-px row bands
#define NTILE     (TILE_COLS * TILE_ROWS)

// ---------------- device scratch (sorted-by-depth gaussian data) ----------------
__device__ float4 g_s0[NG];            // u, v, axx, axy   (log2-space conic, opacity folded)
__device__ float4 g_s1[NG];            // ayy, lo, r, g
__device__ float4 g_scul[NG];          // u, v, rx, ry     (cull bbox)
__device__ float  g_sbl[NG];           // blue
__device__ unsigned short g_tiles[NTILE][NG];  // per-tile ordered index lists
__device__ int    g_tcnt[NTILE];

__device__ __forceinline__ float fast_exp2(float x) {
    float r;
    asm("ex2.approx.f32 %0, %1;" : "=f"(r) : "f"(x));
    return r;
}

// ---------------- kernel 1: preprocess (warp 0) || split rank scan (warps 1-4) ----------------
// 48 blocks x 160 threads. Each block owns 32 gaussians.
__global__ void __launch_bounds__(160) pre_rank_kernel(const float* __restrict__ means,
                                                       const float* __restrict__ quats,
                                                       const float* __restrict__ log_scales,
                                                       const float* __restrict__ opacity_logits,
                                                       const float* __restrict__ sh,
                                                       const float* __restrict__ c2w) {
    __shared__ float skey[NG];
    __shared__ int   srank[NPART][32];

    int tid  = threadIdx.x;
    int warp = tid >> 5;               // 0..4
    int lane = tid & 31;

    // w2c depth row: Wm[2][j] = -c2w[j*4+2]
    float W20 = -c2w[2], W21 = -c2w[6], W22 = -c2w[10];
    float tx0 = c2w[3], ty0 = c2w[7], tz0 = c2w[11];
    float tw2 = -(W20 * tx0 + W21 * ty0 + W22 * tz0);

    for (int i = tid; i < NG; i += 160) {
        float mx = means[3 * i + 0], my = means[3 * i + 1], mz = means[3 * i + 2];
        float d = W20 * mx + W21 * my + W22 * mz + tw2;
        bool mk = (d > NEAR_) && (d < FAR_);
        skey[i] = mk ? d : FINF;
    }
    __syncthreads();

    int n = blockIdx.x * 32 + lane;    // gaussian owned by this lane

    if (warp >= 1) {
        int part = warp - 1;
        float key = skey[n];
        const float4* sk4 = (const float4*)(skey + part * CHUNK);
        int jb0 = part * CHUNK;
        int r0 = 0, r1 = 0, r2 = 0, r3 = 0;
#pragma unroll 4
        for (int j4 = 0; j4 < CHUNK / 4; ++j4) {
            float4 v = sk4[j4];
            int jb = jb0 + j4 * 4;
            r0 += (v.x < key) || ((v.x == key) && (jb + 0 < n));
            r1 += (v.y < key) || ((v.y == key) && (jb + 1 < n));
            r2 += (v.z < key) || ((v.z == key) && (jb + 2 < n));
            r3 += (v.w < key) || ((v.w == key) && (jb + 3 < n));
        }
        srank[part][lane] = (r0 + r1) + (r2 + r3);
        __syncthreads();
        return;
    }

    // ================= warp 0: full preprocess for gaussian n =================
    const float sgn[3] = {1.f, -1.f, -1.f};
    float Wm[3][3];
#pragma unroll
    for (int i = 0; i < 3; ++i)
#pragma unroll
        for (int j = 0; j < 3; ++j)
            Wm[i][j] = c2w[j * 4 + i] * sgn[i];
    float tw[3];
#pragma unroll
    for (int i = 0; i < 3; ++i)
        tw[i] = -(Wm[i][0] * tx0 + Wm[i][1] * ty0 + Wm[i][2] * tz0);

    float mx = means[3 * n + 0], my = means[3 * n + 1], mz = means[3 * n + 2];
    float mc[3];
#pragma unroll
    for (int i = 0; i < 3; ++i)
        mc[i] = Wm[i][0] * mx + Wm[i][1] * my + Wm[i][2] * mz + tw[i];
    float depth = mc[2];
    bool mask = (depth > NEAR_) && (depth < FAR_);

    float dx = mx - tx0, dy = my - ty0, dz = mz - tz0;
    float rn = rsqrtf(dx * dx + dy * dy + dz * dz);
    float x = dx * rn, y = dy * rn, z = dz * rn;

    float basis[16];
    basis[0]  = 0.282095f;
    basis[1]  = -0.488603f * y;
    basis[2]  = 0.488603f * z;
    basis[3]  = -0.488603f * x;
    basis[4]  = 1.092548f * x * y;
    basis[5]  = -1.092548f * y * z;
    basis[6]  = 0.315392f * (3.f * z * z - 1.f);
    basis[7]  = -1.092548f * x * z;
    basis[8]  = 0.546274f * (x * x - y * y);
    basis[9]  = -0.590044f * y * (3.f * x * x - y * y);
    basis[10] = 2.890611f * x * y * z;
    basis[11] = -0.457046f * y * (5.f * z * z - 1.f);
    basis[12] = 0.373176f * z * (5.f * z * z - 3.f);
    basis[13] = -0.457046f * x * (5.f * z * z - 1.f);
    basis[14] = 1.445306f * z * (x * x - y * y);
    basis[15] = -0.590044f * x * (x * x - 3.f * y * y);

    float col[3] = {0.f, 0.f, 0.f};
    const float* shn = sh + n * 48;
#pragma unroll
    for (int k = 0; k < 16; ++k) {
        col[0] = fmaf(basis[k], shn[k * 3 + 0], col[0]);
        col[1] = fmaf(basis[k], shn[k * 3 + 1], col[1]);
        col[2] = fmaf(basis[k], shn[k * 3 + 2], col[2]);
    }
#pragma unroll
    for (int c = 0; c < 3; ++c) col[c] = fmaxf(col[c] + 0.5f, 0.f);

    float qw = quats[4 * n + 0], qx = quats[4 * n + 1], qy = quats[4 * n + 2], qz = quats[4 * n + 3];
    float qn = rsqrtf(qw * qw + qx * qx + qy * qy + qz * qz);
    qw *= qn; qx *= qn; qy *= qn; qz *= qn;
    float Rg[3][3];
    Rg[0][0] = 1.f - 2.f * (qy * qy + qz * qz);
    Rg[0][1] = 2.f * (qx * qy - qz * qw);
    Rg[0][2] = 2.f * (qx * qz + qy * qw);
    Rg[1][0] = 2.f * (qx * qy + qz * qw);
    Rg[1][1] = 1.f - 2.f * (qx * qx + qz * qz);
    Rg[1][2] = 2.f * (qy * qz - qx * qw);
    Rg[2][0] = 2.f * (qx * qz - qy * qw);
    Rg[2][1] = 2.f * (qy * qz + qx * qw);
    Rg[2][2] = 1.f - 2.f * (qx * qx + qy * qy);

    float e0 = expf(log_scales[3 * n + 0]);
    float e1 = expf(log_scales[3 * n + 1]);
    float e2 = expf(log_scales[3 * n + 2]);

    float Mc[3][3];
#pragma unroll
    for (int i = 0; i < 3; ++i) {
        float m0 = Wm[i][0] * Rg[0][0] + Wm[i][1] * Rg[1][0] + Wm[i][2] * Rg[2][0];
        float m1 = Wm[i][0] * Rg[0][1] + Wm[i][1] * Rg[1][1] + Wm[i][2] * Rg[2][1];
        float m2 = Wm[i][0] * Rg[0][2] + Wm[i][1] * Rg[1][2] + Wm[i][2] * Rg[2][2];
        Mc[i][0] = m0 * e0; Mc[i][1] = m1 * e1; Mc[i][2] = m2 * e2;
    }

    float tcx = mc[0], tcy = mc[1], tcz = mc[2];
    float rz = 1.f / tcz;
    float j00 = FX_ * rz, j02 = -FX_ * tcx * rz * rz;
    float j11 = FY_ * rz, j12 = -FY_ * tcy * rz * rz;

    float P0[3], P1[3];
#pragma unroll
    for (int j = 0; j < 3; ++j) {
        P0[j] = j00 * Mc[0][j] + j02 * Mc[2][j];
        P1[j] = j11 * Mc[1][j] + j12 * Mc[2][j];
    }
    float a = P0[0] * P0[0] + P0[1] * P0[1] + P0[2] * P0[2] + EPS2D_;
    float cc = P1[0] * P1[0] + P1[1] * P1[1] + P1[2] * P1[2] + EPS2D_;
    float b = P0[0] * P1[0] + P0[1] * P1[1] + P0[2] * P1[2];
    float det = a * cc - b * b;
    float inv = 1.f / det;
    float A = cc * inv, B = -b * inv, C = a * inv;

    float axx = -0.5f * LOG2E_ * A;
    float ayy = -0.5f * LOG2E_ * C;
    float axy = -LOG2E_ * B;

    float u = FX_ * tcx * rz + CX_;
    float v = FY_ * tcy * rz + CY_;

    float opac = 1.f / (1.f + expf(-opacity_logits[n]));
    float lo = log2f(opac);
    if (!mask) lo = -1e30f;

    float aq = -axx, bq = -axy, cq = -ayy;
    float t = lo - SKIP_THR;
    float rx = -1.f, ry = -1.f;
    if (t > 0.f) {
        float denom = 4.f * aq * cq - bq * bq;
        float rden = 4.f * t / denom;
        rx = sqrtf(cq * rden) + 1.0f;
        ry = sqrtf(aq * rden) + 1.0f;
    }

    __syncthreads();   // wait for scanning warps' partial ranks

    int rank = (srank[0][lane] + srank[1][lane]) + (srank[2][lane] + srank[3][lane]);

    g_s0[rank]   = make_float4(u, v, axx, axy);
    g_s1[rank]   = make_float4(ayy, lo, col[0], col[1]);
    g_scul[rank] = make_float4(u, v, rx, ry);
    g_sbl[rank]  = col[2];
}

// ---------------- kernel 2: tile binning (80 tiles, 1 warp each) ----------------
__global__ void __launch_bounds__(32) bin_kernel() {
    int tile = blockIdx.x;               // 0..79
    int lane = threadIdx.x;
    int tc = tile % TILE_COLS;
    int tr = tile / TILE_COLS;
    float tx0 = (float)(tc * 32);
    float tx1 = tx0 + 31.f;
    float ty0 = (float)(tr * 8);
    float ty1 = ty0 + 7.f;

    int cnt = 0;
#pragma unroll
    for (int r = 0; r < NG / 32; ++r) {
        int g = r * 32 + lane;
        float4 cb = g_scul[g];           // u, v, rx, ry (coalesced)
        bool pass = (cb.x + cb.z > tx0) && (cb.x - cb.z < tx1) &&
                    (cb.y + cb.w > ty0) && (cb.y - cb.w < ty1);
        unsigned m = __ballot_sync(0xffffffffu, pass);
        if (pass)
            g_tiles[tile][cnt + __popc(m & ((1u << lane) - 1u))] = (unsigned short)g;
        cnt += __popc(m);
    }
    if (lane == 0) g_tcnt[tile] = cnt;
}

// ---------------- kernel 3: tile-list culled, segmented per-pixel compositing ----------------
__global__ void __launch_bounds__(32 * NSEG) render_kernel(float* __restrict__ out) {
    int lane = threadIdx.x;              // 0..31  -> pixel within 32-px row strip
    int seg  = threadIdx.y;              // 0..NSEG-1
    int pixbase = blockIdx.x * 32;       // strips never cross rows: 160 = 5*32
    int px0 = pixbase % WID;
    int py  = pixbase / WID;
    int tile = (py >> 3) * TILE_COLS + (px0 >> 5);

    float yc = (float)py;
    float xc = (float)px0 + 15.5f;
    float lx = (float)lane - 15.5f;

    __shared__ unsigned short slist[NSEG][SEGLEN];
    __shared__ float          sblue[NSEG][SEGLEN];
    __shared__ float4         sred[NSEG][32];

    // ---- scan this warp's contiguous sublist of the tile list (order-preserving) ----
    int tcnt = g_tcnt[tile];
    int L  = (tcnt + NSEG - 1) / NSEG;   // <= 96 always (1536/16)
    int s0 = seg * L;
    int s1 = min(tcnt, s0 + L);

    int cnt = 0;
    for (int base = s0; base < s1; base += 32) {
        int idx = base + lane;
        bool valid = (idx < s1);
        int g = valid ? (int)g_tiles[tile][idx] : 0;
        float4 cb = g_scul[g];           // gather (L1/L2 resident, 24KB total)
        bool pass = valid && (fabsf(cb.y - yc) < cb.w);   // x exact at tile granularity
        unsigned m = __ballot_sync(0xffffffffu, pass);
        if (pass) {
            int slot = cnt + __popc(m & ((1u << lane) - 1u));
            slist[seg][slot] = (unsigned short)g;
            sblue[seg][slot] = g_sbl[g];
        }
        cnt += __popc(m);
    }
    __syncwarp();

    // ---- composite survivors (front-to-back within sublist) ----
    float T = 1.f, cr = 0.f, cg = 0.f, cbl = 0.f;
    for (int j = 0; j < cnt; ++j) {
        int g = slist[seg][j];
        float4 a  = __ldg(&g_s0[g]);     // u, v, axx, axy  (broadcast)
        float4 b4 = __ldg(&g_s1[g]);     // ayy, lo, r, g
        float du = xc - a.x;
        float dv = yc - a.y;
        float tx = a.z * du;
        float s  = fmaf(a.w, dv, tx);
        float k0 = fmaf(du, s, b4.y);
        k0 = fmaf(b4.x * dv, dv, k0);
        float k1 = fmaf(a.w, dv, tx + tx);
        float p  = fmaf(fmaf(a.z, lx, k1), lx, k0);
        if (p > SKIP_THR) {
            float alpha = fminf(fast_exp2(p), 0.999f);
            float w = T * alpha;
            cr  = fmaf(w, b4.z, cr);
            cg  = fmaf(w, b4.w, cg);
            cbl = fmaf(w, sblue[seg][j], cbl);
            T   = fmaf(-T, alpha, T);
        }
    }

    sred[seg][lane] = make_float4(T, cr, cg, cbl);
    __syncthreads();

    if (seg == 0) {
        float Tp = 1.f, R = 0.f, G = 0.f, B = 0.f;
#pragma unroll
        for (int k = 0; k < NSEG; ++k) {
            float4 vv = sred[k][lane];
            R = fmaf(Tp, vv.y, R);
            G = fmaf(Tp, vv.z, G);
            B = fmaf(Tp, vv.w, B);
            Tp *= vv.x;
        }
        int pix = pixbase + lane;
        out[pix * 3 + 0] = R;
        out[pix * 3 + 1] = G;
        out[pix * 3 + 2] = B;
    }
}

// ---------------- launch ----------------
extern "C" void kernel_launch(void* const* d_in, const int* in_sizes, int n_in,
                              void* d_out, int out_size) {
    const float* means   = (const float*)d_in[0];
    const float* quats   = (const float*)d_in[1];
    const float* lscales = (const float*)d_in[2];
    const float* opl     = (const float*)d_in[3];
    const float* sh      = (const float*)d_in[4];
    const float* c2w     = (const float*)d_in[5];
    float* out = (float*)d_out;

    pre_rank_kernel<<<48, 160>>>(means, quats, lscales, opl, sh, c2w);
    bin_kernel<<<NTILE, 32>>>();
    render_kernel<<<(WID * HEI) / 32, dim3(32, NSEG)>>>(out);
}

// round 8
// speedup vs baseline: 1.6586x; 1.6586x over previous
#include <cuda_runtime.h>
#include <math.h>

#define NG        1536
#define WID       160
#define HEI       128
#define FX_       146.44f
#define FY_       146.44f
#define CX_       80.0f
#define CY_       64.0f
#define EPS2D_    0.3f
#define NEAR_     0.01f
#define FAR_      1e10f
#define NSEG      16
#define SEGLEN    (NG / NSEG)          // 96
#define LOG2E_    1.4426950408889634f
#define SKIP_THR  (-16.0f)             // log2 units; culled alpha <= 1.5e-5
#define FINF      __int_as_float(0x7f800000)
#define NPART     4                    // rank-scan split factor
#define CHUNK     (NG / NPART)         // 384 keys per scanning thread

// ---------------- device scratch (sorted-by-depth gaussian data) ----------------
__device__ float4 g_s0[NG];            // u, v, axx, axy   (log2-space conic, opacity folded)
__device__ float4 g_s1[NG];            // ayy, lo, r, g
__device__ float4 g_scul[NG];          // u, v, rx, ry     (cull bbox)
__device__ float  g_sbl[NG];           // blue

__device__ __forceinline__ float fast_exp2(float x) {
    float r;
    asm("ex2.approx.f32 %0, %1;" : "=f"(r) : "f"(x));
    return r;
}

// ---------------- kernel 1: preprocess (warp 0) || split rank scan (warps 1-4) ----------------
// 48 blocks x 160 threads. Each block owns 32 gaussians.
__global__ void __launch_bounds__(160) pre_rank_kernel(const float* __restrict__ means,
                                                       const float* __restrict__ quats,
                                                       const float* __restrict__ log_scales,
                                                       const float* __restrict__ opacity_logits,
                                                       const float* __restrict__ sh,
                                                       const float* __restrict__ c2w) {
    __shared__ float skey[NG];
    __shared__ int   srank[NPART][32];

    int tid  = threadIdx.x;
    int warp = tid >> 5;               // 0..4
    int lane = tid & 31;

    // w2c depth row: Wm[2][j] = -c2w[j*4+2]
    float W20 = -c2w[2], W21 = -c2w[6], W22 = -c2w[10];
    float tx0 = c2w[3], ty0 = c2w[7], tz0 = c2w[11];
    float tw2 = -(W20 * tx0 + W21 * ty0 + W22 * tz0);

    // all 160 threads cooperatively compute all depth keys
    for (int i = tid; i < NG; i += 160) {
        float mx = means[3 * i + 0], my = means[3 * i + 1], mz = means[3 * i + 2];
        float d = W20 * mx + W21 * my + W22 * mz + tw2;
        bool mk = (d > NEAR_) && (d < FAR_);
        skey[i] = mk ? d : FINF;
    }
    __syncthreads();

    int n = blockIdx.x * 32 + lane;    // gaussian owned by this lane

    if (warp >= 1) {
        // ---- split rank scan: warp w scans chunk (w-1) for gaussian n ----
        int part = warp - 1;
        float key = skey[n];
        const float4* sk4 = (const float4*)(skey + part * CHUNK);
        int jb0 = part * CHUNK;
        int r0 = 0, r1 = 0, r2 = 0, r3 = 0;
#pragma unroll 4
        for (int j4 = 0; j4 < CHUNK / 4; ++j4) {
            float4 v = sk4[j4];
            int jb = jb0 + j4 * 4;
            r0 += (v.x < key) || ((v.x == key) && (jb + 0 < n));
            r1 += (v.y < key) || ((v.y == key) && (jb + 1 < n));
            r2 += (v.z < key) || ((v.z == key) && (jb + 2 < n));
            r3 += (v.w < key) || ((v.w == key) && (jb + 3 < n));
        }
        srank[part][lane] = (r0 + r1) + (r2 + r3);
        __syncthreads();
        return;
    }

    // ================= warp 0: full preprocess for gaussian n =================
    const float sgn[3] = {1.f, -1.f, -1.f};
    float Wm[3][3];
#pragma unroll
    for (int i = 0; i < 3; ++i)
#pragma unroll
        for (int j = 0; j < 3; ++j)
            Wm[i][j] = c2w[j * 4 + i] * sgn[i];
    float tw[3];
#pragma unroll
    for (int i = 0; i < 3; ++i)
        tw[i] = -(Wm[i][0] * tx0 + Wm[i][1] * ty0 + Wm[i][2] * tz0);

    float mx = means[3 * n + 0], my = means[3 * n + 1], mz = means[3 * n + 2];
    float mc[3];
#pragma unroll
    for (int i = 0; i < 3; ++i)
        mc[i] = Wm[i][0] * mx + Wm[i][1] * my + Wm[i][2] * mz + tw[i];
    float depth = mc[2];
    bool mask = (depth > NEAR_) && (depth < FAR_);

    // view direction
    float dx = mx - tx0, dy = my - ty0, dz = mz - tz0;
    float rn = rsqrtf(dx * dx + dy * dy + dz * dz);
    float x = dx * rn, y = dy * rn, z = dz * rn;

    float basis[16];
    basis[0]  = 0.282095f;
    basis[1]  = -0.488603f * y;
    basis[2]  = 0.488603f * z;
    basis[3]  = -0.488603f * x;
    basis[4]  = 1.092548f * x * y;
    basis[5]  = -1.092548f * y * z;
    basis[6]  = 0.315392f * (3.f * z * z - 1.f);
    basis[7]  = -1.092548f * x * z;
    basis[8]  = 0.546274f * (x * x - y * y);
    basis[9]  = -0.590044f * y * (3.f * x * x - y * y);
    basis[10] = 2.890611f * x * y * z;
    basis[11] = -0.457046f * y * (5.f * z * z - 1.f);
    basis[12] = 0.373176f * z * (5.f * z * z - 3.f);
    basis[13] = -0.457046f * x * (5.f * z * z - 1.f);
    basis[14] = 1.445306f * z * (x * x - y * y);
    basis[15] = -0.590044f * x * (x * x - 3.f * y * y);

    float col[3] = {0.f, 0.f, 0.f};
    const float* shn = sh + n * 48;
#pragma unroll
    for (int k = 0; k < 16; ++k) {
        col[0] = fmaf(basis[k], shn[k * 3 + 0], col[0]);
        col[1] = fmaf(basis[k], shn[k * 3 + 1], col[1]);
        col[2] = fmaf(basis[k], shn[k * 3 + 2], col[2]);
    }
#pragma unroll
    for (int c = 0; c < 3; ++c) col[c] = fmaxf(col[c] + 0.5f, 0.f);

    float qw = quats[4 * n + 0], qx = quats[4 * n + 1], qy = quats[4 * n + 2], qz = quats[4 * n + 3];
    float qn = rsqrtf(qw * qw + qx * qx + qy * qy + qz * qz);
    qw *= qn; qx *= qn; qy *= qn; qz *= qn;
    float Rg[3][3];
    Rg[0][0] = 1.f - 2.f * (qy * qy + qz * qz);
    Rg[0][1] = 2.f * (qx * qy - qz * qw);
    Rg[0][2] = 2.f * (qx * qz + qy * qw);
    Rg[1][0] = 2.f * (qx * qy + qz * qw);
    Rg[1][1] = 1.f - 2.f * (qx * qx + qz * qz);
    Rg[1][2] = 2.f * (qy * qz - qx * qw);
    Rg[2][0] = 2.f * (qx * qz - qy * qw);
    Rg[2][1] = 2.f * (qy * qz + qx * qw);
    Rg[2][2] = 1.f - 2.f * (qx * qx + qy * qy);

    float e0 = expf(log_scales[3 * n + 0]);
    float e1 = expf(log_scales[3 * n + 1]);
    float e2 = expf(log_scales[3 * n + 2]);

    float Mc[3][3];
#pragma unroll
    for (int i = 0; i < 3; ++i) {
        float m0 = Wm[i][0] * Rg[0][0] + Wm[i][1] * Rg[1][0] + Wm[i][2] * Rg[2][0];
        float m1 = Wm[i][0] * Rg[0][1] + Wm[i][1] * Rg[1][1] + Wm[i][2] * Rg[2][1];
        float m2 = Wm[i][0] * Rg[0][2] + Wm[i][1] * Rg[1][2] + Wm[i][2] * Rg[2][2];
        Mc[i][0] = m0 * e0; Mc[i][1] = m1 * e1; Mc[i][2] = m2 * e2;
    }

    float tcx = mc[0], tcy = mc[1], tcz = mc[2];
    float rz = 1.f / tcz;
    float j00 = FX_ * rz, j02 = -FX_ * tcx * rz * rz;
    float j11 = FY_ * rz, j12 = -FY_ * tcy * rz * rz;

    float P0[3], P1[3];
#pragma unroll
    for (int j = 0; j < 3; ++j) {
        P0[j] = j00 * Mc[0][j] + j02 * Mc[2][j];
        P1[j] = j11 * Mc[1][j] + j12 * Mc[2][j];
    }
    float a = P0[0] * P0[0] + P0[1] * P0[1] + P0[2] * P0[2] + EPS2D_;
    float cc = P1[0] * P1[0] + P1[1] * P1[1] + P1[2] * P1[2] + EPS2D_;
    float b = P0[0] * P1[0] + P0[1] * P1[1] + P0[2] * P1[2];
    float det = a * cc - b * b;
    float inv = 1.f / det;
    float A = cc * inv, B = -b * inv, C = a * inv;

    float axx = -0.5f * LOG2E_ * A;
    float ayy = -0.5f * LOG2E_ * C;
    float axy = -LOG2E_ * B;

    float u = FX_ * tcx * rz + CX_;
    float v = FY_ * tcy * rz + CY_;

    float opac = 1.f / (1.f + expf(-opacity_logits[n]));
    float lo = log2f(opac);
    if (!mask) lo = -1e30f;

    // bbox of ellipse p = SKIP_THR
    float aq = -axx, bq = -axy, cq = -ayy;
    float t = lo - SKIP_THR;
    float rx = -1.f, ry = -1.f;
    if (t > 0.f) {
        float denom = 4.f * aq * cq - bq * bq;
        float rden = 4.f * t / denom;
        rx = sqrtf(cq * rden) + 1.0f;
        ry = sqrtf(aq * rden) + 1.0f;
    }

    __syncthreads();   // wait for scanning warps' partial ranks

    int rank = (srank[0][lane] + srank[1][lane]) + (srank[2][lane] + srank[3][lane]);

    g_s0[rank]   = make_float4(u, v, axx, axy);
    g_s1[rank]   = make_float4(ayy, lo, col[0], col[1]);
    g_scul[rank] = make_float4(u, v, rx, ry);
    g_sbl[rank]  = col[2];
}

// ---------------- kernel 2: culled, segmented per-pixel compositing ----------------
__global__ void __launch_bounds__(32 * NSEG) render_kernel(float* __restrict__ out) {
    int lane = threadIdx.x;              // 0..31  -> pixel within 32-px row strip
    int seg  = threadIdx.y;              // 0..NSEG-1 -> gaussian segment
    int pixbase = blockIdx.x * 32;       // strips never cross rows: 160 = 5*32
    int px0 = pixbase % WID;
    int py  = pixbase / WID;

    float yc = (float)py;
    float xc = (float)px0 + 15.5f;
    float lx = (float)lane - 15.5f;
    float fx0 = (float)px0;
    float fx1 = (float)(px0 + 31);

    __shared__ unsigned short slist[NSEG][SEGLEN];
    __shared__ float          sblue[NSEG][SEGLEN];
    __shared__ float4         sred[NSEG][32];

    // ---- scan & compact this warp's segment (coalesced) ----
    int i0 = seg * SEGLEN;
    int cnt = 0;
#pragma unroll
    for (int r = 0; r < SEGLEN / 32; ++r) {
        int g = i0 + r * 32 + lane;
        float4 cb = g_scul[g];           // u, v, rx, ry
        bool pass = (fabsf(cb.y - yc) < cb.w) &&
                    (cb.x + cb.z > fx0) && (cb.x - cb.z < fx1);
        unsigned m = __ballot_sync(0xffffffffu, pass);
        if (pass) {
            int slot = cnt + __popc(m & ((1u << lane) - 1u));
            slist[seg][slot] = (unsigned short)g;
            sblue[seg][slot] = g_sbl[g];
        }
        cnt += __popc(m);
    }
    __syncwarp();

    // ---- composite survivors: branchless (underflowed exp2 -> alpha = 0 -> no-op) ----
    float T = 1.f, cr = 0.f, cg = 0.f, cbl = 0.f;
    for (int j = 0; j < cnt; ++j) {
        int g = slist[seg][j];
        float4 a  = __ldg(&g_s0[g]);     // u, v, axx, axy  (broadcast)
        float4 b4 = __ldg(&g_s1[g]);     // ayy, lo, r, g
        float du = xc - a.x;             // uniform across warp
        float dv = yc - a.y;
        float tx = a.z * du;
        float s  = fmaf(a.w, dv, tx);
        float k0 = fmaf(du, s, b4.y);
        k0 = fmaf(b4.x * dv, dv, k0);
        float k1 = fmaf(a.w, dv, tx + tx);
        float p  = fmaf(fmaf(a.z, lx, k1), lx, k0);
        float alpha = fminf(fast_exp2(p), 0.999f);
        float w = T * alpha;
        cr  = fmaf(w, b4.z, cr);
        cg  = fmaf(w, b4.w, cg);
        cbl = fmaf(w, sblue[seg][j], cbl);
        T   = fmaf(-T, alpha, T);
    }

    sred[seg][lane] = make_float4(T, cr, cg, cbl);
    __syncthreads();

    if (seg == 0) {
        float Tp = 1.f, R = 0.f, G = 0.f, B = 0.f;
#pragma unroll
        for (int k = 0; k < NSEG; ++k) {
            float4 vv = sred[k][lane];
            R = fmaf(Tp, vv.y, R);
            G = fmaf(Tp, vv.z, G);
            B = fmaf(Tp, vv.w, B);
            Tp *= vv.x;
        }
        int pix = pixbase + lane;
        out[pix * 3 + 0] = R;
        out[pix * 3 + 1] = G;
        out[pix * 3 + 2] = B;
    }
}

// ---------------- launch ----------------
extern "C" void kernel_launch(void* const* d_in, const int* in_sizes, int n_in,
                              void* d_out, int out_size) {
    const float* means   = (const float*)d_in[0];
    const float* quats   = (const float*)d_in[1];
    const float* lscales = (const float*)d_in[2];
    const float* opl     = (const float*)d_in[3];
    const float* sh      = (const float*)d_in[4];
    const float* c2w     = (const float*)d_in[5];
    float* out = (float*)d_out;

    pre_rank_kernel<<<48, 160>>>(means, quats, lscales, opl, sh, c2w);
    render_kernel<<<(WID * HEI) / 32, dim3(32, NSEG)>>>(out);
}

// round 9
// speedup vs baseline: 1.6814x; 1.0137x over previous
#include <cuda_runtime.h>
#include <math.h>

#define NG        1536
#define WID       160
#define HEI       128
#define FX_       146.44f
#define FY_       146.44f
#define CX_       80.0f
#define CY_       64.0f
#define EPS2D_    0.3f
#define NEAR_     0.01f
#define FAR_      1e10f
#define NSEG      16
#define SEGLEN    (NG / NSEG)          // 96
#define LOG2E_    1.4426950408889634f
#define SKIP_THR  (-16.0f)             // log2 units; culled alpha <= 1.5e-5
#define FINF      __int_as_float(0x7f800000)
#define NPART     4                    // rank-scan split factor
#define CHUNK     (NG / NPART)         // 384 keys per scanning thread

// ---------------- device scratch (sorted-by-depth gaussian data) ----------------
__device__ float4 g_s0[NG];            // u, v, axx, axy   (log2-space conic, opacity folded)
__device__ float4 g_s1[NG];            // ayy, lo, r, g
__device__ float4 g_scul[NG];          // u, v, rx, ry     (cull bbox)
__device__ float  g_sbl[NG];           // blue

__device__ __forceinline__ float fast_exp2(float x) {
    float r;
    asm("ex2.approx.f32 %0, %1;" : "=f"(r) : "f"(x));
    return r;
}

// ---------------- kernel 1: preprocess (warp 0) || split rank scan (warps 1-4) ----------------
// 48 blocks x 160 threads. Each block owns 32 gaussians.
__global__ void __launch_bounds__(160) pre_rank_kernel(const float* __restrict__ means,
                                                       const float* __restrict__ quats,
                                                       const float* __restrict__ log_scales,
                                                       const float* __restrict__ opacity_logits,
                                                       const float* __restrict__ sh,
                                                       const float* __restrict__ c2w) {
    __shared__ float skey[NG];
    __shared__ int   srank[NPART][32];

    int tid  = threadIdx.x;
    int warp = tid >> 5;               // 0..4
    int lane = tid & 31;

    // w2c depth row: Wm[2][j] = -c2w[j*4+2]
    float W20 = -c2w[2], W21 = -c2w[6], W22 = -c2w[10];
    float tx0 = c2w[3], ty0 = c2w[7], tz0 = c2w[11];
    float tw2 = -(W20 * tx0 + W21 * ty0 + W22 * tz0);

    // all 160 threads cooperatively compute all depth keys
    for (int i = tid; i < NG; i += 160) {
        float mx = means[3 * i + 0], my = means[3 * i + 1], mz = means[3 * i + 2];
        float d = W20 * mx + W21 * my + W22 * mz + tw2;
        bool mk = (d > NEAR_) && (d < FAR_);
        skey[i] = mk ? d : FINF;
    }
    __syncthreads();

    int n = blockIdx.x * 32 + lane;    // gaussian owned by this lane

    if (warp >= 1) {
        // ---- split rank scan: warp w scans chunk (w-1) for gaussian n ----
        int part = warp - 1;
        float key = skey[n];
        const float4* sk4 = (const float4*)(skey + part * CHUNK);
        int jb0 = part * CHUNK;
        int r0 = 0, r1 = 0, r2 = 0, r3 = 0;
#pragma unroll 4
        for (int j4 = 0; j4 < CHUNK / 4; ++j4) {
            float4 v = sk4[j4];
            int jb = jb0 + j4 * 4;
            r0 += (v.x < key) || ((v.x == key) && (jb + 0 < n));
            r1 += (v.y < key) || ((v.y == key) && (jb + 1 < n));
            r2 += (v.z < key) || ((v.z == key) && (jb + 2 < n));
            r3 += (v.w < key) || ((v.w == key) && (jb + 3 < n));
        }
        srank[part][lane] = (r0 + r1) + (r2 + r3);
        __syncthreads();
        return;
    }

    // ================= warp 0: full preprocess for gaussian n =================
    const float sgn[3] = {1.f, -1.f, -1.f};
    float Wm[3][3];
#pragma unroll
    for (int i = 0; i < 3; ++i)
#pragma unroll
        for (int j = 0; j < 3; ++j)
            Wm[i][j] = c2w[j * 4 + i] * sgn[i];
    float tw[3];
#pragma unroll
    for (int i = 0; i < 3; ++i)
        tw[i] = -(Wm[i][0] * tx0 + Wm[i][1] * ty0 + Wm[i][2] * tz0);

    float mx = means[3 * n + 0], my = means[3 * n + 1], mz = means[3 * n + 2];
    float mc[3];
#pragma unroll
    for (int i = 0; i < 3; ++i)
        mc[i] = Wm[i][0] * mx + Wm[i][1] * my + Wm[i][2] * mz + tw[i];
    float depth = mc[2];
    bool mask = (depth > NEAR_) && (depth < FAR_);

    // view direction
    float dx = mx - tx0, dy = my - ty0, dz = mz - tz0;
    float rn = rsqrtf(dx * dx + dy * dy + dz * dz);
    float x = dx * rn, y = dy * rn, z = dz * rn;

    float basis[16];
    basis[0]  = 0.282095f;
    basis[1]  = -0.488603f * y;
    basis[2]  = 0.488603f * z;
    basis[3]  = -0.488603f * x;
    basis[4]  = 1.092548f * x * y;
    basis[5]  = -1.092548f * y * z;
    basis[6]  = 0.315392f * (3.f * z * z - 1.f);
    basis[7]  = -1.092548f * x * z;
    basis[8]  = 0.546274f * (x * x - y * y);
    basis[9]  = -0.590044f * y * (3.f * x * x - y * y);
    basis[10] = 2.890611f * x * y * z;
    basis[11] = -0.457046f * y * (5.f * z * z - 1.f);
    basis[12] = 0.373176f * z * (5.f * z * z - 3.f);
    basis[13] = -0.457046f * x * (5.f * z * z - 1.f);
    basis[14] = 1.445306f * z * (x * x - y * y);
    basis[15] = -0.590044f * x * (x * x - 3.f * y * y);

    float col[3] = {0.f, 0.f, 0.f};
    const float* shn = sh + n * 48;
#pragma unroll
    for (int k = 0; k < 16; ++k) {
        col[0] = fmaf(basis[k], shn[k * 3 + 0], col[0]);
        col[1] = fmaf(basis[k], shn[k * 3 + 1], col[1]);
        col[2] = fmaf(basis[k], shn[k * 3 + 2], col[2]);
    }
#pragma unroll
    for (int c = 0; c < 3; ++c) col[c] = fmaxf(col[c] + 0.5f, 0.f);

    float qw = quats[4 * n + 0], qx = quats[4 * n + 1], qy = quats[4 * n + 2], qz = quats[4 * n + 3];
    float qn = rsqrtf(qw * qw + qx * qx + qy * qy + qz * qz);
    qw *= qn; qx *= qn; qy *= qn; qz *= qn;
    float Rg[3][3];
    Rg[0][0] = 1.f - 2.f * (qy * qy + qz * qz);
    Rg[0][1] = 2.f * (qx * qy - qz * qw);
    Rg[0][2] = 2.f * (qx * qz + qy * qw);
    Rg[1][0] = 2.f * (qx * qy + qz * qw);
    Rg[1][1] = 1.f - 2.f * (qx * qx + qz * qz);
    Rg[1][2] = 2.f * (qy * qz - qx * qw);
    Rg[2][0] = 2.f * (qx * qz - qy * qw);
    Rg[2][1] = 2.f * (qy * qz + qx * qw);
    Rg[2][2] = 1.f - 2.f * (qx * qx + qy * qy);

    float e0 = expf(log_scales[3 * n + 0]);
    float e1 = expf(log_scales[3 * n + 1]);
    float e2 = expf(log_scales[3 * n + 2]);

    float Mc[3][3];
#pragma unroll
    for (int i = 0; i < 3; ++i) {
        float m0 = Wm[i][0] * Rg[0][0] + Wm[i][1] * Rg[1][0] + Wm[i][2] * Rg[2][0];
        float m1 = Wm[i][0] * Rg[0][1] + Wm[i][1] * Rg[1][1] + Wm[i][2] * Rg[2][1];
        float m2 = Wm[i][0] * Rg[0][2] + Wm[i][1] * Rg[1][2] + Wm[i][2] * Rg[2][2];
        Mc[i][0] = m0 * e0; Mc[i][1] = m1 * e1; Mc[i][2] = m2 * e2;
    }

    float tcx = mc[0], tcy = mc[1], tcz = mc[2];
    float rz = 1.f / tcz;
    float j00 = FX_ * rz, j02 = -FX_ * tcx * rz * rz;
    float j11 = FY_ * rz, j12 = -FY_ * tcy * rz * rz;

    float P0[3], P1[3];
#pragma unroll
    for (int j = 0; j < 3; ++j) {
        P0[j] = j00 * Mc[0][j] + j02 * Mc[2][j];
        P1[j] = j11 * Mc[1][j] + j12 * Mc[2][j];
    }
    float a = P0[0] * P0[0] + P0[1] * P0[1] + P0[2] * P0[2] + EPS2D_;
    float cc = P1[0] * P1[0] + P1[1] * P1[1] + P1[2] * P1[2] + EPS2D_;
    float b = P0[0] * P1[0] + P0[1] * P1[1] + P0[2] * P1[2];
    float det = a * cc - b * b;
    float inv = 1.f / det;
    float A = cc * inv, B = -b * inv, C = a * inv;

    float axx = -0.5f * LOG2E_ * A;
    float ayy = -0.5f * LOG2E_ * C;
    float axy = -LOG2E_ * B;

    float u = FX_ * tcx * rz + CX_;
    float v = FY_ * tcy * rz + CY_;

    float opac = 1.f / (1.f + expf(-opacity_logits[n]));
    float lo = log2f(opac);
    if (!mask) lo = -1e30f;

    // bbox of ellipse p = SKIP_THR
    float aq = -axx, bq = -axy, cq = -ayy;
    float t = lo - SKIP_THR;
    float rx = -1.f, ry = -1.f;
    if (t > 0.f) {
        float denom = 4.f * aq * cq - bq * bq;
        float rden = 4.f * t / denom;
        rx = sqrtf(cq * rden) + 1.0f;
        ry = sqrtf(aq * rden) + 1.0f;
    }

    __syncthreads();   // wait for scanning warps' partial ranks

    int rank = (srank[0][lane] + srank[1][lane]) + (srank[2][lane] + srank[3][lane]);

    g_s0[rank]   = make_float4(u, v, axx, axy);
    g_s1[rank]   = make_float4(ayy, lo, col[0], col[1]);
    g_scul[rank] = make_float4(u, v, rx, ry);
    g_sbl[rank]  = col[2];
}

// ---------------- kernel 2: culled, segmented per-pixel compositing ----------------
// __launch_bounds__(512, 4): force <=32 regs so 4 blocks/SM co-reside (occupancy
// is what feeds this kernel; R8 showed branchless at 47% occ == branchy at 82%).
__global__ void __launch_bounds__(32 * NSEG, 4) render_kernel(float* __restrict__ out) {
    int lane = threadIdx.x;              // 0..31  -> pixel within 32-px row strip
    int seg  = threadIdx.y;              // 0..NSEG-1 -> gaussian segment
    int pixbase = blockIdx.x * 32;       // strips never cross rows: 160 = 5*32
    int px0 = pixbase % WID;
    int py  = pixbase / WID;

    float yc = (float)py;
    float xc = (float)px0 + 15.5f;
    float lx = (float)lane - 15.5f;
    float fx0 = (float)px0;
    float fx1 = (float)(px0 + 31);

    __shared__ unsigned short slist[NSEG][SEGLEN];
    __shared__ float          sblue[NSEG][SEGLEN];
    __shared__ float4         sred[NSEG][32];

    // ---- scan & compact this warp's segment (coalesced) ----
    int i0 = seg * SEGLEN;
    int cnt = 0;
#pragma unroll
    for (int r = 0; r < SEGLEN / 32; ++r) {
        int g = i0 + r * 32 + lane;
        float4 cb = g_scul[g];           // u, v, rx, ry
        bool pass = (fabsf(cb.y - yc) < cb.w) &&
                    (cb.x + cb.z > fx0) && (cb.x - cb.z < fx1);
        unsigned m = __ballot_sync(0xffffffffu, pass);
        if (pass) {
            int slot = cnt + __popc(m & ((1u << lane) - 1u));
            slist[seg][slot] = (unsigned short)g;
            sblue[seg][slot] = g_sbl[g];
        }
        cnt += __popc(m);
    }
    __syncwarp();

    // ---- composite survivors: branchless (underflowed exp2 -> alpha = 0 -> no-op) ----
    float T = 1.f, cr = 0.f, cg = 0.f, cbl = 0.f;
    for (int j = 0; j < cnt; ++j) {
        int g = slist[seg][j];
        float4 a  = __ldg(&g_s0[g]);     // u, v, axx, axy  (broadcast)
        float4 b4 = __ldg(&g_s1[g]);     // ayy, lo, r, g
        float du = xc - a.x;             // uniform across warp
        float dv = yc - a.y;
        float tx = a.z * du;
        float s  = fmaf(a.w, dv, tx);
        float k0 = fmaf(du, s, b4.y);
        k0 = fmaf(b4.x * dv, dv, k0);
        float k1 = fmaf(a.w, dv, tx + tx);
        float p  = fmaf(fmaf(a.z, lx, k1), lx, k0);
        float alpha = fminf(fast_exp2(p), 0.999f);
        float w = T * alpha;
        cr  = fmaf(w, b4.z, cr);
        cg  = fmaf(w, b4.w, cg);
        cbl = fmaf(w, sblue[seg][j], cbl);
        T   = fmaf(-T, alpha, T);
    }

    sred[seg][lane] = make_float4(T, cr, cg, cbl);
    __syncthreads();

    if (seg == 0) {
        float Tp = 1.f, R = 0.f, G = 0.f, B = 0.f;
#pragma unroll
        for (int k = 0; k < NSEG; ++k) {
            float4 vv = sred[k][lane];
            R = fmaf(Tp, vv.y, R);
            G = fmaf(Tp, vv.z, G);
            B = fmaf(Tp, vv.w, B);
            Tp *= vv.x;
        }
        int pix = pixbase + lane;
        out[pix * 3 + 0] = R;
        out[pix * 3 + 1] = G;
        out[pix * 3 + 2] = B;
    }
}

// ---------------- launch ----------------
extern "C" void kernel_launch(void* const* d_in, const int* in_sizes, int n_in,
                              void* d_out, int out_size) {
    const float* means   = (const float*)d_in[0];
    const float* quats   = (const float*)d_in[1];
    const float* lscales = (const float*)d_in[2];
    const float* opl     = (const float*)d_in[3];
    const float* sh      = (const float*)d_in[4];
    const float* c2w     = (const float*)d_in[5];
    float* out = (float*)d_out;

    pre_rank_kernel<<<48, 160>>>(means, quats, lscales, opl, sh, c2w);
    render_kernel<<<(WID * HEI) / 32, dim3(32, NSEG)>>>(out);
}

// round 10
// speedup vs baseline: 1.6943x; 1.0077x over previous
#include <cuda_runtime.h>
#include <math.h>

#define NG        1536
#define WID       160
#define HEI       128
#define FX_       146.44f
#define FY_       146.44f
#define CX_       80.0f
#define CY_       64.0f
#define EPS2D_    0.3f
#define NEAR_     0.01f
#define FAR_      1e10f
#define NSEG      16
#define SEGLEN    (NG / NSEG)          // 96
#define LOG2E_    1.4426950408889634f
#define SKIP_THR  (-16.0f)             // log2 units; culled alpha <= 1.5e-5
#define FINF      __int_as_float(0x7f800000)
#define NPART     4                    // rank-scan split factor
#define CHUNK     (NG / NPART)         // 384 keys per scanning thread

// ---------------- device scratch (sorted-by-depth gaussian data) ----------------
__device__ float4 g_s0[NG];            // u, v, axx, axy   (log2-space conic, opacity folded)
__device__ float4 g_s1[NG];            // ayy, lo, r, g
__device__ float4 g_scul[NG];          // u, v, rx, ry     (cull bbox)
__device__ float  g_sbl[NG];           // blue

__device__ __forceinline__ float fast_exp2(float x) {
    float r;
    asm("ex2.approx.f32 %0, %1;" : "=f"(r) : "f"(x));
    return r;
}

// ---------------- kernel 1: preprocess (warp 0) || split rank scan (warps 1-4) ----------------
// 48 blocks x 160 threads. Each block owns 32 gaussians.
__global__ void __launch_bounds__(160) pre_rank_kernel(const float* __restrict__ means,
                                                       const float* __restrict__ quats,
                                                       const float* __restrict__ log_scales,
                                                       const float* __restrict__ opacity_logits,
                                                       const float* __restrict__ sh,
                                                       const float* __restrict__ c2w) {
    __shared__ float skey[NG];
    __shared__ int   srank[NPART][32];

    int tid  = threadIdx.x;
    int warp = tid >> 5;               // 0..4
    int lane = tid & 31;

    // w2c depth row: Wm[2][j] = -c2w[j*4+2]
    float W20 = -c2w[2], W21 = -c2w[6], W22 = -c2w[10];
    float tx0 = c2w[3], ty0 = c2w[7], tz0 = c2w[11];
    float tw2 = -(W20 * tx0 + W21 * ty0 + W22 * tz0);

    // all 160 threads cooperatively compute all depth keys
    for (int i = tid; i < NG; i += 160) {
        float mx = means[3 * i + 0], my = means[3 * i + 1], mz = means[3 * i + 2];
        float d = W20 * mx + W21 * my + W22 * mz + tw2;
        bool mk = (d > NEAR_) && (d < FAR_);
        skey[i] = mk ? d : FINF;
    }
    __syncthreads();

    int n = blockIdx.x * 32 + lane;    // gaussian owned by this lane

    if (warp >= 1) {
        // ---- split rank scan: warp w scans chunk (w-1) for gaussian n ----
        int part = warp - 1;
        float key = skey[n];
        const float4* sk4 = (const float4*)(skey + part * CHUNK);
        int jb0 = part * CHUNK;
        int r0 = 0, r1 = 0, r2 = 0, r3 = 0;
#pragma unroll 4
        for (int j4 = 0; j4 < CHUNK / 4; ++j4) {
            float4 v = sk4[j4];
            int jb = jb0 + j4 * 4;
            r0 += (v.x < key) || ((v.x == key) && (jb + 0 < n));
            r1 += (v.y < key) || ((v.y == key) && (jb + 1 < n));
            r2 += (v.z < key) || ((v.z == key) && (jb + 2 < n));
            r3 += (v.w < key) || ((v.w == key) && (jb + 3 < n));
        }
        srank[part][lane] = (r0 + r1) + (r2 + r3);
        __syncthreads();
        return;
    }

    // ================= warp 0: full preprocess for gaussian n =================
    const float sgn[3] = {1.f, -1.f, -1.f};
    float Wm[3][3];
#pragma unroll
    for (int i = 0; i < 3; ++i)
#pragma unroll
        for (int j = 0; j < 3; ++j)
            Wm[i][j] = c2w[j * 4 + i] * sgn[i];
    float tw[3];
#pragma unroll
    for (int i = 0; i < 3; ++i)
        tw[i] = -(Wm[i][0] * tx0 + Wm[i][1] * ty0 + Wm[i][2] * tz0);

    float mx = means[3 * n + 0], my = means[3 * n + 1], mz = means[3 * n + 2];
    float mc[3];
#pragma unroll
    for (int i = 0; i < 3; ++i)
        mc[i] = Wm[i][0] * mx + Wm[i][1] * my + Wm[i][2] * mz + tw[i];
    float depth = mc[2];
    bool mask = (depth > NEAR_) && (depth < FAR_);

    // view direction
    float dx = mx - tx0, dy = my - ty0, dz = mz - tz0;
    float rn = rsqrtf(dx * dx + dy * dy + dz * dz);
    float x = dx * rn, y = dy * rn, z = dz * rn;

    float basis[16];
    basis[0]  = 0.282095f;
    basis[1]  = -0.488603f * y;
    basis[2]  = 0.488603f * z;
    basis[3]  = -0.488603f * x;
    basis[4]  = 1.092548f * x * y;
    basis[5]  = -1.092548f * y * z;
    basis[6]  = 0.315392f * (3.f * z * z - 1.f);
    basis[7]  = -1.092548f * x * z;
    basis[8]  = 0.546274f * (x * x - y * y);
    basis[9]  = -0.590044f * y * (3.f * x * x - y * y);
    basis[10] = 2.890611f * x * y * z;
    basis[11] = -0.457046f * y * (5.f * z * z - 1.f);
    basis[12] = 0.373176f * z * (5.f * z * z - 3.f);
    basis[13] = -0.457046f * x * (5.f * z * z - 1.f);
    basis[14] = 1.445306f * z * (x * x - y * y);
    basis[15] = -0.590044f * x * (x * x - 3.f * y * y);

    float col[3] = {0.f, 0.f, 0.f};
    const float* shn = sh + n * 48;
#pragma unroll
    for (int k = 0; k < 16; ++k) {
        col[0] = fmaf(basis[k], shn[k * 3 + 0], col[0]);
        col[1] = fmaf(basis[k], shn[k * 3 + 1], col[1]);
        col[2] = fmaf(basis[k], shn[k * 3 + 2], col[2]);
    }
#pragma unroll
    for (int c = 0; c < 3; ++c) col[c] = fmaxf(col[c] + 0.5f, 0.f);

    float qw = quats[4 * n + 0], qx = quats[4 * n + 1], qy = quats[4 * n + 2], qz = quats[4 * n + 3];
    float qn = rsqrtf(qw * qw + qx * qx + qy * qy + qz * qz);
    qw *= qn; qx *= qn; qy *= qn; qz *= qn;
    float Rg[3][3];
    Rg[0][0] = 1.f - 2.f * (qy * qy + qz * qz);
    Rg[0][1] = 2.f * (qx * qy - qz * qw);
    Rg[0][2] = 2.f * (qx * qz + qy * qw);
    Rg[1][0] = 2.f * (qx * qy + qz * qw);
    Rg[1][1] = 1.f - 2.f * (qx * qx + qz * qz);
    Rg[1][2] = 2.f * (qy * qz - qx * qw);
    Rg[2][0] = 2.f * (qx * qz - qy * qw);
    Rg[2][1] = 2.f * (qy * qz + qx * qw);
    Rg[2][2] = 1.f - 2.f * (qx * qx + qy * qy);

    float e0 = expf(log_scales[3 * n + 0]);
    float e1 = expf(log_scales[3 * n + 1]);
    float e2 = expf(log_scales[3 * n + 2]);

    float Mc[3][3];
#pragma unroll
    for (int i = 0; i < 3; ++i) {
        float m0 = Wm[i][0] * Rg[0][0] + Wm[i][1] * Rg[1][0] + Wm[i][2] * Rg[2][0];
        float m1 = Wm[i][0] * Rg[0][1] + Wm[i][1] * Rg[1][1] + Wm[i][2] * Rg[2][1];
        float m2 = Wm[i][0] * Rg[0][2] + Wm[i][1] * Rg[1][2] + Wm[i][2] * Rg[2][2];
        Mc[i][0] = m0 * e0; Mc[i][1] = m1 * e1; Mc[i][2] = m2 * e2;
    }

    float tcx = mc[0], tcy = mc[1], tcz = mc[2];
    float rz = 1.f / tcz;
    float j00 = FX_ * rz, j02 = -FX_ * tcx * rz * rz;
    float j11 = FY_ * rz, j12 = -FY_ * tcy * rz * rz;

    float P0[3], P1[3];
#pragma unroll
    for (int j = 0; j < 3; ++j) {
        P0[j] = j00 * Mc[0][j] + j02 * Mc[2][j];
        P1[j] = j11 * Mc[1][j] + j12 * Mc[2][j];
    }
    float a = P0[0] * P0[0] + P0[1] * P0[1] + P0[2] * P0[2] + EPS2D_;
    float cc = P1[0] * P1[0] + P1[1] * P1[1] + P1[2] * P1[2] + EPS2D_;
    float b = P0[0] * P1[0] + P0[1] * P1[1] + P0[2] * P1[2];
    float det = a * cc - b * b;
    float inv = 1.f / det;
    float A = cc * inv, B = -b * inv, C = a * inv;

    float axx = -0.5f * LOG2E_ * A;
    float ayy = -0.5f * LOG2E_ * C;
    float axy = -LOG2E_ * B;

    float u = FX_ * tcx * rz + CX_;
    float v = FY_ * tcy * rz + CY_;

    float opac = 1.f / (1.f + expf(-opacity_logits[n]));
    float lo = log2f(opac);
    if (!mask) lo = -1e30f;

    // bbox of ellipse p = SKIP_THR
    float aq = -axx, bq = -axy, cq = -ayy;
    float t = lo - SKIP_THR;
    float rx = -1.f, ry = -1.f;
    if (t > 0.f) {
        float denom = 4.f * aq * cq - bq * bq;
        float rden = 4.f * t / denom;
        rx = sqrtf(cq * rden) + 1.0f;
        ry = sqrtf(aq * rden) + 1.0f;
    }

    __syncthreads();   // wait for scanning warps' partial ranks

    int rank = (srank[0][lane] + srank[1][lane]) + (srank[2][lane] + srank[3][lane]);

    g_s0[rank]   = make_float4(u, v, axx, axy);
    g_s1[rank]   = make_float4(ayy, lo, col[0], col[1]);
    g_scul[rank] = make_float4(u, v, rx, ry);
    g_sbl[rank]  = col[2];
}

// ---------------- kernel 2: culled, load-balanced per-pixel compositing ----------------
// 640 blocks x 512 threads (unchanged occupancy). Per-segment cull lists are
// concatenated (depth order preserved) and re-split into 16 EQUAL spans so the
// block barrier waits on mean work, not max work.
__global__ void __launch_bounds__(32 * NSEG, 4) render_kernel(float* __restrict__ out) {
    int lane = threadIdx.x;              // 0..31  -> pixel within 32-px row strip
    int seg  = threadIdx.y;              // 0..NSEG-1
    int pixbase = blockIdx.x * 32;       // strips never cross rows: 160 = 5*32
    int px0 = pixbase % WID;
    int py  = pixbase / WID;

    float yc = (float)py;
    float xc = (float)px0 + 15.5f;
    float lx = (float)lane - 15.5f;
    float fx0 = (float)px0;
    float fx1 = (float)(px0 + 31);

    __shared__ unsigned short slist[NSEG][SEGLEN];
    __shared__ int   scnt[NSEG];
    __shared__ int   soff[NSEG + 1];
    __shared__ unsigned short glist[NG];
    __shared__ float gblue[NG];
    __shared__ float4 sred[NSEG][32];

    // ---- phase 1: per-segment cull & compact (coalesced; preserves order) ----
    int i0 = seg * SEGLEN;
    int cnt = 0;
#pragma unroll
    for (int r = 0; r < SEGLEN / 32; ++r) {
        int g = i0 + r * 32 + lane;
        float4 cb = g_scul[g];           // u, v, rx, ry
        bool pass = (fabsf(cb.y - yc) < cb.w) &&
                    (cb.x + cb.z > fx0) && (cb.x - cb.z < fx1);
        unsigned m = __ballot_sync(0xffffffffu, pass);
        if (pass)
            slist[seg][cnt + __popc(m & ((1u << lane) - 1u))] = (unsigned short)g;
        cnt += __popc(m);
    }
    if (lane == 0) scnt[seg] = cnt;
    __syncthreads();

    // ---- phase 2: prefix sum over segment counts, concat into block list ----
    if (seg == 0) {
        int c = (lane < NSEG) ? scnt[lane] : 0;
#pragma unroll
        for (int d = 1; d < NSEG; d <<= 1) {
            int t = __shfl_up_sync(0xffffffffu, c, d);
            if (lane >= d) c += t;
        }
        if (lane < NSEG) soff[lane + 1] = c;
        if (lane == 0) soff[0] = 0;
    }
    __syncthreads();

    int off = soff[seg];
    for (int j = lane; j < cnt; j += 32) {
        unsigned short g = slist[seg][j];
        glist[off + j] = g;
        gblue[off + j] = g_sbl[g];
    }
    __syncthreads();

    // ---- phase 3: balanced composite over equal spans (branchless) ----
    int S  = soff[NSEG];
    int L  = (S + NSEG - 1) / NSEG;
    int s0 = seg * L;
    int s1 = min(S, s0 + L);

    float T = 1.f, cr = 0.f, cg = 0.f, cbl = 0.f;
    for (int j = s0; j < s1; ++j) {
        int g = glist[j];
        float4 a  = __ldg(&g_s0[g]);     // u, v, axx, axy  (broadcast)
        float4 b4 = __ldg(&g_s1[g]);     // ayy, lo, r, g
        float du = xc - a.x;             // uniform across warp
        float dv = yc - a.y;
        float tx = a.z * du;
        float s  = fmaf(a.w, dv, tx);
        float k0 = fmaf(du, s, b4.y);
        k0 = fmaf(b4.x * dv, dv, k0);
        float k1 = fmaf(a.w, dv, tx + tx);
        float p  = fmaf(fmaf(a.z, lx, k1), lx, k0);
        float alpha = fminf(fast_exp2(p), 0.999f);
        float w = T * alpha;
        cr  = fmaf(w, b4.z, cr);
        cg  = fmaf(w, b4.w, cg);
        cbl = fmaf(w, gblue[j], cbl);
        T   = fmaf(-T, alpha, T);
    }

    sred[seg][lane] = make_float4(T, cr, cg, cbl);
    __syncthreads();

    // ---- phase 4: ordered chain of the 16 spans ----
    if (seg == 0) {
        float Tp = 1.f, R = 0.f, G = 0.f, B = 0.f;
#pragma unroll
        for (int k = 0; k < NSEG; ++k) {
            float4 vv = sred[k][lane];
            R = fmaf(Tp, vv.y, R);
            G = fmaf(Tp, vv.z, G);
            B = fmaf(Tp, vv.w, B);
            Tp *= vv.x;
        }
        int pix = pixbase + lane;
        out[pix * 3 + 0] = R;
        out[pix * 3 + 1] = G;
        out[pix * 3 + 2] = B;
    }
}

// ---------------- launch ----------------
extern "C" void kernel_launch(void* const* d_in, const int* in_sizes, int n_in,
                              void* d_out, int out_size) {
    const float* means   = (const float*)d_in[0];
    const float* quats   = (const float*)d_in[1];
    const float* lscales = (const float*)d_in[2];
    const float* opl     = (const float*)d_in[3];
    const float* sh      = (const float*)d_in[4];
    const float* c2w     = (const float*)d_in[5];
    float* out = (float*)d_out;

    pre_rank_kernel<<<48, 160>>>(means, quats, lscales, opl, sh, c2w);
    render_kernel<<<(WID * HEI) / 32, dim3(32, NSEG)>>>(out);
}